// round 2
// baseline (speedup 1.0000x reference)
#include <cuda_runtime.h>

#define NRES  384
#define NSEQ  256
#define NFEAT 64
#define NPROJ 32
#define NOUT  128
#define ICDIM (NRES * NPROJ)      // 12288
#define LN_EPS 1e-5f

#define TM 128                    // O-tile dim (4 res * 32 proj)
#define KC 8                      // k-chunk for GEMM1
#define OSTRIDE 132               // padded O-tile smem stride (floats, /4 aligned)
#define WSTRIDE 68                // padded Wo-chunk smem stride (floats, /4 aligned)
#define KC2 64                    // k-chunk for GEMM2 (over cd=1024)
#define SMEM_FLOATS (TM * OSTRIDE + NOUT * WSTRIDE)   // 16896 + 8704 = 25600
#define SMEM_BYTES  (SMEM_FLOATS * 4)                 // 102400

// scratch (device globals: allocation-free per harness rules)
__device__ float g_L[NSEQ * ICDIM];        // [s][i*32+c], masked left
__device__ float g_R[NSEQ * ICDIM];        // [s][j*32+d], masked right
__device__ float g_norm[NRES * NRES];      // mask gram

// ---------------------------------------------------------------------------
// Kernel 1: LayerNorm + both projections + mask, one row (s,i) per warp.
// ---------------------------------------------------------------------------
__global__ void prep_kernel(const float* __restrict__ M,
                            const float* __restrict__ mask,
                            const float* __restrict__ gamma,
                            const float* __restrict__ beta,
                            const float* __restrict__ Wa,
                            const float* __restrict__ ba,
                            const float* __restrict__ Wb,
                            const float* __restrict__ bb)
{
    __shared__ float sWa[NPROJ * NFEAT];
    __shared__ float sWb[NPROJ * NFEAT];
    __shared__ float rowbuf[8][NFEAT];

    for (int idx = threadIdx.x; idx < NPROJ * NFEAT; idx += blockDim.x) {
        sWa[idx] = Wa[idx];
        sWb[idx] = Wb[idx];
    }
    __syncthreads();

    const int warp = threadIdx.x >> 5;
    const int lane = threadIdx.x & 31;
    const int nw   = blockDim.x >> 5;
    const int gw   = blockIdx.x * nw + warp;
    const int totw = gridDim.x * nw;
    const int nrows = NSEQ * NRES;

    const float g0 = gamma[lane], g1 = gamma[lane + 32];
    const float be0 = beta[lane], be1 = beta[lane + 32];
    const float bal = ba[lane], bbl = bb[lane];

    for (int row = gw; row < nrows; row += totw) {
        float f0 = M[row * NFEAT + lane];
        float f1 = M[row * NFEAT + 32 + lane];
        float s1 = f0 + f1;
        float s2 = f0 * f0 + f1 * f1;
        #pragma unroll
        for (int off = 16; off > 0; off >>= 1) {
            s1 += __shfl_xor_sync(0xFFFFFFFFu, s1, off);
            s2 += __shfl_xor_sync(0xFFFFFFFFu, s2, off);
        }
        float mu  = s1 * (1.0f / 64.0f);
        float var = s2 * (1.0f / 64.0f) - mu * mu;
        float inv = rsqrtf(var + LN_EPS);

        rowbuf[warp][lane]      = (f0 - mu) * inv * g0 + be0;
        rowbuf[warp][lane + 32] = (f1 - mu) * inv * g1 + be1;
        __syncwarp();

        float la = bal, rb = bbl;
        #pragma unroll
        for (int f = 0; f < NFEAT; f++) {
            float v = rowbuf[warp][f];
            la += v * sWa[lane * NFEAT + f];
            rb += v * sWb[lane * NFEAT + f];
        }
        float m = mask[row];
        g_L[row * NPROJ + lane] = m * la;
        g_R[row * NPROJ + lane] = m * rb;
        __syncwarp();
    }
}

// ---------------------------------------------------------------------------
// Kernel 2: norm[i,j] = sum_s mask[s,i]*mask[s,j]
// ---------------------------------------------------------------------------
__global__ void norm_kernel(const float* __restrict__ mask)
{
    const int i = blockIdx.x;
    const int j = threadIdx.x;
    float acc = 0.0f;
    for (int s = 0; s < NSEQ; s++)
        acc += mask[s * NRES + i] * mask[s * NRES + j];
    g_norm[i * NRES + j] = acc;
}

// ---------------------------------------------------------------------------
// Kernel 3: fused GEMM1 (O-tile 128x128 over K=256) + GEMM2 epilogue (Wo) +
// scale + residual. Grid: (96 j-tiles, 96 i-tiles), 256 threads.
// ---------------------------------------------------------------------------
extern __shared__ float smem[];

__global__ void __launch_bounds__(256, 2)
fused_kernel(const float* __restrict__ Zraw,
             const float* __restrict__ Wo,
             const float* __restrict__ bo,
             float* __restrict__ out)
{
    float* As = smem;            // [KC][TM] aliased into O-tile region
    float* Bs = smem + KC * TM;

    const int jt = blockIdx.x;
    const int it = blockIdx.y;
    const int t  = threadIdx.x;
    const int tx = t & 15;
    const int ty = t >> 4;

    const float* Abase = g_L + it * TM;   // row stride ICDIM
    const float* Bbase = g_R + jt * TM;

    const int ldrow = t >> 5;             // 0..7 (one row per warp)
    const int ldcol = (t & 31) << 2;      // 0..124, float4

    // prefetch chunk 0
    float4 ga = *(const float4*)(Abase + ldrow * ICDIM + ldcol);
    float4 gb = *(const float4*)(Bbase + ldrow * ICDIM + ldcol);

    float acc[8][8];
    #pragma unroll
    for (int i = 0; i < 8; i++)
        #pragma unroll
        for (int j = 0; j < 8; j++)
            acc[i][j] = 0.0f;

    // -------- GEMM1 mainloop: O[ic][jd] = sum_s L[s][ic] * R[s][jd] --------
    #pragma unroll 1
    for (int kc = 0; kc < NSEQ / KC; kc++) {
        __syncthreads();
        *(float4*)(As + ldrow * TM + ldcol) = ga;
        *(float4*)(Bs + ldrow * TM + ldcol) = gb;
        __syncthreads();
        if (kc + 1 < NSEQ / KC) {
            const float* An = Abase + (kc + 1) * KC * ICDIM + ldrow * ICDIM + ldcol;
            const float* Bn = Bbase + (kc + 1) * KC * ICDIM + ldrow * ICDIM + ldcol;
            ga = *(const float4*)An;
            gb = *(const float4*)Bn;
        }
        #pragma unroll
        for (int k = 0; k < KC; k++) {
            float4 a0 = *(const float4*)(As + k * TM + (ty << 2));
            float4 a1 = *(const float4*)(As + k * TM + 64 + (ty << 2));
            float4 b0 = *(const float4*)(Bs + k * TM + (tx << 2));
            float4 b1 = *(const float4*)(Bs + k * TM + 64 + (tx << 2));
            float av[8] = {a0.x, a0.y, a0.z, a0.w, a1.x, a1.y, a1.z, a1.w};
            float bv[8] = {b0.x, b0.y, b0.z, b0.w, b1.x, b1.y, b1.z, b1.w};
            #pragma unroll
            for (int i = 0; i < 8; i++)
                #pragma unroll
                for (int j = 0; j < 8; j++)
                    acc[i][j] += av[i] * bv[j];
        }
    }
    __syncthreads();   // mainloop reads done; safe to overwrite As/Bs as O-tile

    // -------- stage O-tile to smem --------
    float* Osm = smem;                       // [TM][OSTRIDE]
    #pragma unroll
    for (int ih = 0; ih < 2; ih++) {
        #pragma unroll
        for (int rr = 0; rr < 4; rr++) {
            int row = ih * 64 + (ty << 2) + rr;
            #pragma unroll
            for (int jh = 0; jh < 2; jh++) {
                float4 v;
                v.x = acc[ih * 4 + rr][jh * 4 + 0];
                v.y = acc[ih * 4 + rr][jh * 4 + 1];
                v.z = acc[ih * 4 + rr][jh * 4 + 2];
                v.w = acc[ih * 4 + rr][jh * 4 + 3];
                *(float4*)(Osm + row * OSTRIDE + jh * 64 + (tx << 2)) = v;
            }
        }
    }

    // -------- GEMM2 epilogue: Z[pair][o] = sum_{cd} O * Wo[o][cd] --------
    float* Wos = smem + TM * OSTRIDE;        // [NOUT][WSTRIDE]

    const int og = t & 31;                   // o-group (o = og + 32*oo)
    const int pg = t >> 5;                   // pairs pg and pg+8 (warp-uniform)
    const int p0 = pg, p1 = pg + 8;
    const int il0 = p0 >> 2, jl0 = p0 & 3;
    const int il1 = p1 >> 2, jl1 = p1 & 3;

    float zacc[2][4];
    #pragma unroll
    for (int pp = 0; pp < 2; pp++)
        #pragma unroll
        for (int oo = 0; oo < 4; oo++)
            zacc[pp][oo] = 0.0f;

    #pragma unroll 1
    for (int kc = 0; kc < (NPROJ * NPROJ) / KC2; kc++) {   // 16 chunks
        __syncthreads();
        // stage Wo[:, kc*64 .. +64) into smem (coalesced rows)
        #pragma unroll
        for (int pass = 0; pass < 8; pass++) {
            int r  = pass * 16 + (t >> 4);
            int cb = (t & 15) << 2;
            *(float4*)(Wos + r * WSTRIDE + cb) =
                *(const float4*)(Wo + r * (NPROJ * NPROJ) + kc * KC2 + cb);
        }
        __syncthreads();

        #pragma unroll
        for (int c2 = 0; c2 < 2; c2++) {
            int c = kc * 2 + c2;
            int row0 = il0 * 32 + c;
            int row1 = il1 * 32 + c;
            #pragma unroll
            for (int d4 = 0; d4 < 8; d4++) {
                float4 ov0 = *(const float4*)(Osm + row0 * OSTRIDE + jl0 * 32 + (d4 << 2));
                float4 ov1 = *(const float4*)(Osm + row1 * OSTRIDE + jl1 * 32 + (d4 << 2));
                int klb = c2 * 32 + (d4 << 2);
                #pragma unroll
                for (int oo = 0; oo < 4; oo++) {
                    int o = og + 32 * oo;
                    float4 w = *(const float4*)(Wos + o * WSTRIDE + klb);
                    zacc[0][oo] += ov0.x * w.x + ov0.y * w.y + ov0.z * w.z + ov0.w * w.w;
                    zacc[1][oo] += ov1.x * w.x + ov1.y * w.y + ov1.z * w.z + ov1.w * w.w;
                }
            }
        }
    }

    // -------- finalize: (z + bo)/(0.001+norm) + Z_raw --------
    const int i0 = it * 4, j0 = jt * 4;
    #pragma unroll
    for (int pp = 0; pp < 2; pp++) {
        int p = pg + pp * 8;
        int i = i0 + (p >> 2);
        int j = j0 + (p & 3);
        float invn = 1.0f / (0.001f + g_norm[i * NRES + j]);
        size_t base = ((size_t)i * NRES + j) * NOUT;
        #pragma unroll
        for (int oo = 0; oo < 4; oo++) {
            int o = og + 32 * oo;
            out[base + o] = (zacc[pp][oo] + bo[o]) * invn + Zraw[base + o];
        }
    }
}

// ---------------------------------------------------------------------------
extern "C" void kernel_launch(void* const* d_in, const int* in_sizes, int n_in,
                              void* d_out, int out_size)
{
    const float* M     = (const float*)d_in[0];
    const float* mask  = (const float*)d_in[1];
    const float* Zraw  = (const float*)d_in[2];
    const float* gamma = (const float*)d_in[3];
    const float* beta  = (const float*)d_in[4];
    const float* Wa    = (const float*)d_in[5];
    const float* ba    = (const float*)d_in[6];
    const float* Wb    = (const float*)d_in[7];
    const float* bb    = (const float*)d_in[8];
    const float* Wo    = (const float*)d_in[9];
    const float* bo    = (const float*)d_in[10];
    float* out = (float*)d_out;

    cudaFuncSetAttribute(fused_kernel,
                         cudaFuncAttributeMaxDynamicSharedMemorySize, SMEM_BYTES);

    prep_kernel<<<512, 256>>>(M, mask, gamma, beta, Wa, ba, Wb, bb);
    norm_kernel<<<NRES, NRES>>>(mask);
    fused_kernel<<<dim3(NRES / 4, NRES / 4), 256, SMEM_BYTES>>>(Zraw, Wo, bo, out);
}

// round 4
// speedup vs baseline: 5.8631x; 5.8631x over previous
#include <cuda_runtime.h>
#include <cuda_bf16.h>
#include <cstdint>

#define NRES  384
#define NSEQ  256
#define NFEAT 64
#define NPROJ 32
#define NOUT  128
#define ICDIM (NRES*NPROJ)          // 12288
#define NPAIR (NRES*NRES)           // 147456
#define CD    (NPROJ*NPROJ)         // 1024
#define LN_EPS 1e-5f

// ------------------------- scratch (device globals) -------------------------
__device__ __nv_bfloat16 g_Lt[(size_t)ICDIM*NSEQ];   // [m=(i,c)][s]  K-major
__device__ __nv_bfloat16 g_Rt[(size_t)ICDIM*NSEQ];   // [n=(j,d)][s]  K-major
__device__ __nv_bfloat16 g_O [(size_t)NPAIR*CD];     // [(i,j)][(c,d)]
__device__ __nv_bfloat16 g_Wob[NOUT*CD];             // Wo bf16 [o][cd]
__device__ float         g_normv[NPAIR];

// ------------------------- helpers -------------------------
__device__ __forceinline__ uint32_t smem_u32(const void* p){
    uint32_t a;
    asm("{ .reg .u64 t; cvta.to.shared.u64 t, %1; cvt.u32.u64 %0, t; }":"=r"(a):"l"(p));
    return a;
}
__device__ __forceinline__ void ldsm4(uint32_t& r0, uint32_t& r1, uint32_t& r2, uint32_t& r3, uint32_t a){
    asm volatile("ldmatrix.sync.aligned.m8n8.x4.shared.b16 {%0,%1,%2,%3}, [%4];"
        : "=r"(r0),"=r"(r1),"=r"(r2),"=r"(r3) : "r"(a));
}
__device__ __forceinline__ void mma16816(float* c, const uint32_t* a, uint32_t b0, uint32_t b1){
    asm volatile("mma.sync.aligned.m16n8k16.row.col.f32.bf16.bf16.f32 "
        "{%0,%1,%2,%3}, {%4,%5,%6,%7}, {%8,%9}, {%0,%1,%2,%3};"
        : "+f"(c[0]),"+f"(c[1]),"+f"(c[2]),"+f"(c[3])
        : "r"(a[0]),"r"(a[1]),"r"(a[2]),"r"(a[3]),"r"(b0),"r"(b1));
}
__device__ __forceinline__ uint32_t packbf2(float a, float b){
    __nv_bfloat162 h = __floats2bfloat162_rn(a, b);
    return *(uint32_t*)&h;
}

// ---------------------------------------------------------------------------
// prep: LN + projections + mask; write transposed bf16 g_Lt/g_Rt.
// grid=384 (block per residue i), 256 threads (thread per s).
// ---------------------------------------------------------------------------
#define PREP_SMEM (4096*4 + 2*8192*2)   // 49152
__global__ void __launch_bounds__(256,2)
prep_kernel(const float* __restrict__ M, const float* __restrict__ mask,
            const float* __restrict__ gamma, const float* __restrict__ beta,
            const float* __restrict__ Wa, const float* __restrict__ ba,
            const float* __restrict__ Wb, const float* __restrict__ bb)
{
    extern __shared__ float ps[];
    float* sWa = ps;
    float* sWb = ps + 2048;
    __nv_bfloat16* sLb = (__nv_bfloat16*)(ps + 4096);  // [32][256]
    __nv_bfloat16* sRb = sLb + 8192;

    const int i = blockIdx.x;
    const int tid = threadIdx.x;
    for (int u = tid; u < NPROJ*NFEAT; u += 256){ sWa[u] = Wa[u]; sWb[u] = Wb[u]; }

    const int s = tid;
    const float4* mr = (const float4*)(M + ((size_t)s*NRES + i)*NFEAT);
    float4 mn[16];
    float s1 = 0.f, s2 = 0.f;
    #pragma unroll
    for (int q = 0; q < 16; q++){
        float4 v = mr[q]; mn[q] = v;
        s1 += v.x + v.y + v.z + v.w;
        s2 += v.x*v.x + v.y*v.y + v.z*v.z + v.w*v.w;
    }
    float mu  = s1 * (1.f/64.f);
    float var = s2 * (1.f/64.f) - mu*mu;
    float inv = rsqrtf(var + LN_EPS);
    const float4* g4 = (const float4*)gamma;
    const float4* b4 = (const float4*)beta;
    #pragma unroll
    for (int q = 0; q < 16; q++){
        float4 gg = g4[q], be = b4[q];
        mn[q].x = (mn[q].x - mu)*inv*gg.x + be.x;
        mn[q].y = (mn[q].y - mu)*inv*gg.y + be.y;
        mn[q].z = (mn[q].z - mu)*inv*gg.z + be.z;
        mn[q].w = (mn[q].w - mu)*inv*gg.w + be.w;
    }
    const float msk = mask[(size_t)s*NRES + i];
    __syncthreads();

    #pragma unroll 4
    for (int c = 0; c < NPROJ; c++){
        float accA = ba[c], accB = bb[c];
        const float4* wa = (const float4*)(sWa + c*NFEAT);
        const float4* wb = (const float4*)(sWb + c*NFEAT);
        #pragma unroll
        for (int q = 0; q < 16; q++){
            float4 w1 = wa[q], w2 = wb[q], v = mn[q];
            accA += v.x*w1.x + v.y*w1.y + v.z*w1.z + v.w*w1.w;
            accB += v.x*w2.x + v.y*w2.y + v.z*w2.z + v.w*w2.w;
        }
        sLb[c*256 + s] = __float2bfloat16(msk*accA);
        sRb[c*256 + s] = __float2bfloat16(msk*accB);
    }
    __syncthreads();

    for (int u = tid; u < NPROJ*128; u += 256){
        int c = u >> 7, sp = (u & 127) << 1;
        *(uint32_t*)(g_Lt + ((size_t)(i*NPROJ + c))*NSEQ + sp) = *(const uint32_t*)(sLb + c*256 + sp);
        *(uint32_t*)(g_Rt + ((size_t)(i*NPROJ + c))*NSEQ + sp) = *(const uint32_t*)(sRb + c*256 + sp);
    }
}

// ---------------------------------------------------------------------------
__global__ void norm_kernel(const float* __restrict__ mask)
{
    const int i = blockIdx.x, j = threadIdx.x;
    float acc = 0.0f;
    for (int s = 0; s < NSEQ; s++)
        acc += mask[s*NRES + i] * mask[s*NRES + j];
    g_normv[i*NRES + j] = acc;
}

__global__ void wconv_kernel(const float* __restrict__ Wo)
{
    int idx = blockIdx.x*256 + threadIdx.x;
    g_Wob[idx] = __float2bfloat16(Wo[idx]);
}

// ---------------------------------------------------------------------------
// gemm1: O[128x128 tile] = Lt[it*128..][k] * Rt[jt*128..][k]^T, K=256.
// mma.sync bf16, smem K-chunked x2 (64KB), XOR-swizzled for ldmatrix.
// grid=(96,96), 256 threads, occupancy 2.
// ---------------------------------------------------------------------------
#define G1_SMEM (2*32768)
__global__ void __launch_bounds__(256,2) gemm1_kernel()
{
    extern __shared__ char sm1[];
    const int tid = threadIdx.x, lane = tid & 31, w = tid >> 5;
    const int it = blockIdx.y, jt = blockIdx.x;
    const int wr = w >> 2, wc = w & 3;
    const int m0 = wr*64, n0 = wc*32;
    const int lo7 = lane & 7, hi = lane >> 4, l15 = lane & 15;

    const uint32_t sAu = smem_u32(sm1);
    const uint32_t sBu = sAu + 32768;

    float acc[4][4][4];
    #pragma unroll
    for (int a = 0; a < 4; a++)
        #pragma unroll
        for (int b = 0; b < 4; b++)
            #pragma unroll
            for (int c = 0; c < 4; c++) acc[a][b][c] = 0.f;

    #pragma unroll 1
    for (int kc = 0; kc < 2; kc++){
        __syncthreads();
        #pragma unroll
        for (int q = 0; q < 8; q++){
            int u = q*256 + tid;          // 2048 16B-units per matrix
            int row = u >> 4, c = u & 15;
            int cp = c ^ (row & 7);
            *(uint4*)(sm1 + row*256 + cp*16) =
                *(const uint4*)(g_Lt + ((size_t)(it*128 + row))*NSEQ + kc*128 + c*8);
            *(uint4*)(sm1 + 32768 + row*256 + cp*16) =
                *(const uint4*)(g_Rt + ((size_t)(jt*128 + row))*NSEQ + kc*128 + c*8);
        }
        __syncthreads();
        #pragma unroll
        for (int ks = 0; ks < 8; ks++){
            int ch = ((ks*2 + hi) ^ lo7) << 4;
            uint32_t a[4][4], b[2][4];
            #pragma unroll
            for (int mt = 0; mt < 4; mt++)
                ldsm4(a[mt][0],a[mt][1],a[mt][2],a[mt][3],
                      sAu + (m0 + mt*16 + l15)*256 + ch);
            #pragma unroll
            for (int nb = 0; nb < 2; nb++)
                ldsm4(b[nb][0],b[nb][1],b[nb][2],b[nb][3],
                      sBu + (n0 + nb*16 + l15)*256 + ch);
            #pragma unroll
            for (int mt = 0; mt < 4; mt++){
                #pragma unroll
                for (int nb = 0; nb < 2; nb++){
                    mma16816(acc[mt][nb*2],   a[mt], b[nb][0], b[nb][2]);
                    mma16816(acc[mt][nb*2+1], a[mt], b[nb][1], b[nb][3]);
                }
            }
        }
    }

    // epilogue -> g_O[(i*384+j)*1024 + c*32 + d] bf16
    const int rbase = lane >> 2, cpair = (lane & 3)*2;
    const int j = jt*4 + wc;
    #pragma unroll
    for (int mt = 0; mt < 4; mt++){
        int mg0 = it*128 + m0 + mt*16 + rbase;
        int mg1 = mg0 + 8;
        size_t base0 = (((size_t)(mg0 >> 5)*NRES + j) << 10) + ((mg0 & 31) << 5);
        size_t base1 = (((size_t)(mg1 >> 5)*NRES + j) << 10) + ((mg1 & 31) << 5);
        #pragma unroll
        for (int nt = 0; nt < 4; nt++){
            int d = nt*8 + cpair;
            *(uint32_t*)(g_O + base0 + d) = packbf2(acc[mt][nt][0], acc[mt][nt][1]);
            *(uint32_t*)(g_O + base1 + d) = packbf2(acc[mt][nt][2], acc[mt][nt][3]);
        }
    }
}

// ---------------------------------------------------------------------------
// gemm2: Z[m,o] = sum_k O[m,k]*Wob[o,k], m tile 128, o=128, K=1024 chunked x16.
// fused epilogue: (z+bo)*invn + Zraw. grid=1152, 256 threads, occupancy 2.
// ---------------------------------------------------------------------------
#define G2_SMEM (2*16384)
__global__ void __launch_bounds__(256,2)
gemm2_kernel(const float* __restrict__ Zraw, const float* __restrict__ bo,
             float* __restrict__ out)
{
    extern __shared__ char sm2[];
    __shared__ float sbo[NOUT];
    const int tid = threadIdx.x, lane = tid & 31, w = tid >> 5;
    const int m0 = blockIdx.x * 128;
    const int wr = w >> 2, wc = w & 3;
    const int mw0 = wr*64, o0 = wc*32;
    const int lo7 = lane & 7, hi = lane >> 4, l15 = lane & 15;

    const uint32_t sAu = smem_u32(sm2);
    const uint32_t sBu = sAu + 16384;
    if (tid < NOUT) sbo[tid] = bo[tid];

    float acc[4][4][4];
    #pragma unroll
    for (int a = 0; a < 4; a++)
        #pragma unroll
        for (int b = 0; b < 4; b++)
            #pragma unroll
            for (int c = 0; c < 4; c++) acc[a][b][c] = 0.f;

    #pragma unroll 1
    for (int kc = 0; kc < 16; kc++){
        __syncthreads();
        #pragma unroll
        for (int q = 0; q < 4; q++){
            int u = q*256 + tid;          // 1024 16B-units per matrix
            int row = u >> 3, c = u & 7;
            int cp = c ^ (row & 7);
            *(uint4*)(sm2 + row*128 + cp*16) =
                *(const uint4*)(g_O + (size_t)(m0 + row)*CD + kc*64 + c*8);
            *(uint4*)(sm2 + 16384 + row*128 + cp*16) =
                *(const uint4*)(g_Wob + (size_t)row*CD + kc*64 + c*8);
        }
        __syncthreads();
        #pragma unroll
        for (int ks = 0; ks < 4; ks++){
            int ch = ((ks*2 + hi) ^ lo7) << 4;
            uint32_t a[4][4], b[2][4];
            #pragma unroll
            for (int mt = 0; mt < 4; mt++)
                ldsm4(a[mt][0],a[mt][1],a[mt][2],a[mt][3],
                      sAu + (mw0 + mt*16 + l15)*128 + ch);
            #pragma unroll
            for (int nb = 0; nb < 2; nb++)
                ldsm4(b[nb][0],b[nb][1],b[nb][2],b[nb][3],
                      sBu + (o0 + nb*16 + l15)*128 + ch);
            #pragma unroll
            for (int mt = 0; mt < 4; mt++){
                #pragma unroll
                for (int nb = 0; nb < 2; nb++){
                    mma16816(acc[mt][nb*2],   a[mt], b[nb][0], b[nb][2]);
                    mma16816(acc[mt][nb*2+1], a[mt], b[nb][1], b[nb][3]);
                }
            }
        }
    }

    // fused epilogue
    const int rbase = lane >> 2, cpair = (lane & 3)*2;
    #pragma unroll
    for (int mt = 0; mt < 4; mt++){
        int mA = m0 + mw0 + mt*16 + rbase;
        int mB = mA + 8;
        float invA = 1.0f / (0.001f + g_normv[mA]);
        float invB = 1.0f / (0.001f + g_normv[mB]);
        #pragma unroll
        for (int nt = 0; nt < 4; nt++){
            int o = o0 + nt*8 + cpair;
            float b0 = sbo[o], b1 = sbo[o+1];
            float2 zA = *(const float2*)(Zraw + (size_t)mA*NOUT + o);
            float2 zB = *(const float2*)(Zraw + (size_t)mB*NOUT + o);
            float2 rA, rB;
            rA.x = (acc[mt][nt][0] + b0)*invA + zA.x;
            rA.y = (acc[mt][nt][1] + b1)*invA + zA.y;
            rB.x = (acc[mt][nt][2] + b0)*invB + zB.x;
            rB.y = (acc[mt][nt][3] + b1)*invB + zB.y;
            *(float2*)(out + (size_t)mA*NOUT + o) = rA;
            *(float2*)(out + (size_t)mB*NOUT + o) = rB;
        }
    }
}

// ---------------------------------------------------------------------------
extern "C" void kernel_launch(void* const* d_in, const int* in_sizes, int n_in,
                              void* d_out, int out_size)
{
    const float* M     = (const float*)d_in[0];
    const float* mask  = (const float*)d_in[1];
    const float* Zraw  = (const float*)d_in[2];
    const float* gamma = (const float*)d_in[3];
    const float* beta  = (const float*)d_in[4];
    const float* Wa    = (const float*)d_in[5];
    const float* ba    = (const float*)d_in[6];
    const float* Wb    = (const float*)d_in[7];
    const float* bb    = (const float*)d_in[8];
    const float* Wo    = (const float*)d_in[9];
    const float* bo    = (const float*)d_in[10];
    float* out = (float*)d_out;

    cudaFuncSetAttribute(prep_kernel,  cudaFuncAttributeMaxDynamicSharedMemorySize, PREP_SMEM);
    cudaFuncSetAttribute(gemm1_kernel, cudaFuncAttributeMaxDynamicSharedMemorySize, G1_SMEM);
    cudaFuncSetAttribute(gemm2_kernel, cudaFuncAttributeMaxDynamicSharedMemorySize, G2_SMEM);

    prep_kernel<<<NRES, 256, PREP_SMEM>>>(M, mask, gamma, beta, Wa, ba, Wb, bb);
    norm_kernel<<<NRES, NRES>>>(mask);
    wconv_kernel<<<512, 256>>>(Wo);
    gemm1_kernel<<<dim3(96, 96), 256, G1_SMEM>>>();
    gemm2_kernel<<<NPAIR/128, 256, G2_SMEM>>>(Zraw, bo, out);
}